// round 13
// baseline (speedup 1.0000x reference)
#include <cuda_runtime.h>
#include <cuda_bf16.h>
#include <math.h>
#include <stdint.h>

#define Bn 32768
#define Dn 256
#define KN 32
#define FFn 1024

__device__ float g_x[Bn * Dn];
__device__ uint4 g_wqf[16 * 32 * 32];
__device__ uint4 g_wof[16 * 32 * 32];
__device__ uint4 g_wkf[8 * 2 * 32 * 32];
__device__ uint4 g_wvf[8 * 16 * 4 * 32];
__device__ uint4 g_w1f[16 * 128 * 32];
__device__ uint4 g_w2f[64 * 32 * 32];

// ---- attn smem layout (float offsets) ----
#define SM_H  0                // hS  [8][268]
#define SM_QS 2144             // qS  [8][268]  (later oS)
#define SM_CB 4288             // cB uint4 [8][16][32] -> later uB uint2 [64][130]
#define SM_SS 20928            // sS  [64][33]
#define SM_AB 23040            // aB uint2 [64][16]  (split attn pairs)
#define ATTN_SMEM (25152 * 4)  // ~100 KB -> 2 CTAs/SM

// ---- ffn smem (uint2 = packed {hi_pair, lo_pair}) ----
#define FH2 134                // hHL [32][134]
#define FA2 131                // act [32][131]   (256-col chunk)
#define FFN_SMEM ((32 * FH2 + 32 * FA2) * 8)

__device__ __forceinline__ void mmabf(float* c, const uint32_t* a, const uint32_t* b) {
    asm volatile(
        "mma.sync.aligned.m16n8k16.row.col.f32.bf16.bf16.f32 "
        "{%0,%1,%2,%3}, {%4,%5,%6,%7}, {%8,%9}, {%0,%1,%2,%3};"
        : "+f"(c[0]), "+f"(c[1]), "+f"(c[2]), "+f"(c[3])
        : "r"(a[0]), "r"(a[1]), "r"(a[2]), "r"(a[3]), "r"(b[0]), "r"(b[1]));
}

__device__ __forceinline__ uint2 bsplit2(float x, float y) {
    __nv_bfloat16 hx = __float2bfloat16(x), hy = __float2bfloat16(y);
    float rx = x - __bfloat162float(hx), ry = y - __bfloat162float(hy);
    __nv_bfloat16 lx = __float2bfloat16(rx), ly = __float2bfloat16(ry);
    uint2 r;
    r.x = ((uint32_t)__bfloat16_as_ushort(hy) << 16) | __bfloat16_as_ushort(hx);
    r.y = ((uint32_t)__bfloat16_as_ushort(ly) << 16) | __bfloat16_as_ushort(lx);
    return r;
}

__device__ __forceinline__ void asplit(float f0, float f1, uint32_t& hi, uint32_t& lo) {
    uint2 p = bsplit2(f0, f1);
    hi = p.x; lo = p.y;
}

// ---------------------------------------------------------------------------
__global__ void split_all(
    const float* __restrict__ Wq, const float* __restrict__ Wk,
    const float* __restrict__ Wv, const float* __restrict__ Wo,
    const float* __restrict__ ff1w, const float* __restrict__ ff2w)
{
    int gid = blockIdx.x * 256 + threadIdx.x;
    int lane, lg, lc;
    if (gid < 16384) {                                    // Wq
        int e = gid;
        lane = e & 31; lg = lane >> 2; lc = lane & 3;
        int t = e >> 5, ntile = t & 31, ks = t >> 5;
        int k0 = ks * 16 + 2 * lc, n = ntile * 8 + lg;
        uint2 p0 = bsplit2(Wq[k0 * 256 + n], Wq[(k0 + 1) * 256 + n]);
        uint2 p1 = bsplit2(Wq[(k0 + 8) * 256 + n], Wq[(k0 + 9) * 256 + n]);
        g_wqf[e] = make_uint4(p0.x, p0.y, p1.x, p1.y);
    } else if (gid < 32768) {                             // Wo
        int e = gid - 16384;
        lane = e & 31; lg = lane >> 2; lc = lane & 3;
        int t = e >> 5, ntile = t & 31, ks = t >> 5;
        int k0 = ks * 16 + 2 * lc, n = ntile * 8 + lg;
        uint2 p0 = bsplit2(Wo[k0 * 256 + n], Wo[(k0 + 1) * 256 + n]);
        uint2 p1 = bsplit2(Wo[(k0 + 8) * 256 + n], Wo[(k0 + 9) * 256 + n]);
        g_wof[e] = make_uint4(p0.x, p0.y, p1.x, p1.y);
    } else if (gid < 49152) {                             // Wk per head
        int e = gid - 32768;
        lane = e & 31; lg = lane >> 2; lc = lane & 3;
        int t = e >> 5, ntile = t & 31, hk = t >> 5;
        int h = hk >> 1, ks2 = hk & 1;
        int k0 = ks2 * 16 + 2 * lc, n = ntile * 8 + lg;
        const float* base = Wk + n * 256 + h * 32;
        uint2 p0 = bsplit2(base[k0], base[k0 + 1]);
        uint2 p1 = bsplit2(base[k0 + 8], base[k0 + 9]);
        g_wkf[e] = make_uint4(p0.x, p0.y, p1.x, p1.y);
    } else if (gid < 65536) {                             // Wv per head
        int e = gid - 49152;
        lane = e & 31; lg = lane >> 2; lc = lane & 3;
        int t = e >> 5, nt = t & 3, u2 = t >> 2;
        int ks = u2 & 15, hd = u2 >> 4;
        int k0 = ks * 16 + 2 * lc, n = hd * 32 + nt * 8 + lg;
        uint2 p0 = bsplit2(Wv[k0 * 256 + n], Wv[(k0 + 1) * 256 + n]);
        uint2 p1 = bsplit2(Wv[(k0 + 8) * 256 + n], Wv[(k0 + 9) * 256 + n]);
        g_wvf[e] = make_uint4(p0.x, p0.y, p1.x, p1.y);
    } else if (gid < 131072) {                            // ff1w
        int e = gid - 65536;
        lane = e & 31; lg = lane >> 2; lc = lane & 3;
        int t = e >> 5, ntile = t & 127, ks = t >> 7;
        int k0 = ks * 16 + 2 * lc, n = ntile * 8 + lg;
        uint2 p0 = bsplit2(ff1w[k0 * FFn + n], ff1w[(k0 + 1) * FFn + n]);
        uint2 p1 = bsplit2(ff1w[(k0 + 8) * FFn + n], ff1w[(k0 + 9) * FFn + n]);
        g_w1f[e] = make_uint4(p0.x, p0.y, p1.x, p1.y);
    } else if (gid < 196608) {                            // ff2w
        int e = gid - 131072;
        lane = e & 31; lg = lane >> 2; lc = lane & 3;
        int t = e >> 5, ntile = t & 31, ks = t >> 5;
        int k0 = ks * 16 + 2 * lc, n = ntile * 8 + lg;
        uint2 p0 = bsplit2(ff2w[k0 * 256 + n], ff2w[(k0 + 1) * 256 + n]);
        uint2 p1 = bsplit2(ff2w[(k0 + 8) * 256 + n], ff2w[(k0 + 9) * 256 + n]);
        g_w2f[e] = make_uint4(p0.x, p0.y, p1.x, p1.y);
    }
}

// ---------------------------------------------------------------------------
// Attention: 8 anchors / CTA, 512 threads, 2 CTAs/SM. All phases bf16 mma
// except softmax.
// ---------------------------------------------------------------------------
__global__ __launch_bounds__(512, 2) void attn12(
    const float* __restrict__ x_anc, const float* __restrict__ x_nei,
    const float* __restrict__ g1, const float* __restrict__ b1)
{
    extern __shared__ float sf[];
    float* hS = sf + SM_H;
    float* qS = sf + SM_QS;                   // later oS
    uint4* cB = (uint4*)(sf + SM_CB);         // [8a][16ks][32lane]
    uint2* uB = (uint2*)(sf + SM_CB);         // later: [64 rows][130 pairs]
    float* sS = sf + SM_SS;
    uint2* aB = (uint2*)(sf + SM_AB);         // [64 rows (a*8+h)][16 pairs]
    float* oS = qS;

    const int tid = threadIdx.x, wid = tid >> 5, lane = tid & 31;
    const int lg = lane >> 2, lc = lane & 3;
    const int b0 = blockIdx.x * 8;

    // ---- LN1 ----
    if (wid < 8) {
        const float* xr = x_anc + (size_t)(b0 + wid) * Dn;
        float4 v0 = *(const float4*)&xr[lane * 8];
        float4 v1 = *(const float4*)&xr[lane * 8 + 4];
        float v[8] = {v0.x, v0.y, v0.z, v0.w, v1.x, v1.y, v1.z, v1.w};
        float s = 0.f, s2 = 0.f;
        #pragma unroll
        for (int t = 0; t < 8; t++) { s += v[t]; s2 += v[t] * v[t]; }
        #pragma unroll
        for (int o = 16; o; o >>= 1) {
            s  += __shfl_xor_sync(0xffffffffu, s,  o);
            s2 += __shfl_xor_sync(0xffffffffu, s2, o);
        }
        const float mu   = s * (1.0f / Dn);
        const float var  = s2 * (1.0f / Dn) - mu * mu;
        const float rstd = rsqrtf(var + 1e-5f);
        #pragma unroll
        for (int t = 0; t < 8; t++) {
            const int c = lane * 8 + t;
            hS[wid * 268 + c] = (v[t] - mu) * rstd * g1[c] + b1[c];
        }
    }
    __syncthreads();

    // ---- Q = h @ Wq (bf16 mma, M=8) ----
    {
        float acc[2][4] = {{0.f,0.f,0.f,0.f},{0.f,0.f,0.f,0.f}};
        #pragma unroll
        for (int ks = 0; ks < 16; ks++) {
            const int kb = ks * 16;
            float2 p0 = *(const float2*)&hS[lg * 268 + kb + 2 * lc];
            float2 p1 = *(const float2*)&hS[lg * 268 + kb + 8 + 2 * lc];
            uint32_t Ah[4], Al[4];
            asplit(p0.x, p0.y, Ah[0], Al[0]);
            asplit(p1.x, p1.y, Ah[2], Al[2]);
            Ah[1] = Al[1] = Ah[3] = Al[3] = 0u;
            #pragma unroll
            for (int nt = 0; nt < 2; nt++) {
                uint4 v = g_wqf[(ks * 32 + wid * 2 + nt) * 32 + lane];
                uint32_t bh[2] = {v.x, v.z}, bl[2] = {v.y, v.w};
                mmabf(acc[nt], Ah, bh);
                mmabf(acc[nt], Ah, bl);
                mmabf(acc[nt], Al, bh);
            }
        }
        __syncthreads();
        #pragma unroll
        for (int nt = 0; nt < 2; nt++) {
            const int col = wid * 16 + nt * 8 + lc * 2;
            qS[lg * 268 + col]     = acc[nt][0];
            qS[lg * 268 + col + 1] = acc[nt][1];
        }
    }
    __syncthreads();

    // ---- c[a][h][:] (bf16 mma per head) -> cB frag table ----
    {
        #pragma unroll
        for (int h = 0; h < 8; h++) {
            float acc[2][4] = {{0.f,0.f,0.f,0.f},{0.f,0.f,0.f,0.f}};
            #pragma unroll
            for (int ks2 = 0; ks2 < 2; ks2++) {
                const int kb = h * 32 + ks2 * 16;
                float2 p0 = *(const float2*)&qS[lg * 268 + kb + 2 * lc];
                float2 p1 = *(const float2*)&qS[lg * 268 + kb + 8 + 2 * lc];
                uint32_t Ah[4], Al[4];
                asplit(p0.x, p0.y, Ah[0], Al[0]);
                asplit(p1.x, p1.y, Ah[2], Al[2]);
                Ah[1] = Al[1] = Ah[3] = Al[3] = 0u;
                #pragma unroll
                for (int nt = 0; nt < 2; nt++) {
                    uint4 v = g_wkf[((h * 2 + ks2) * 32 + wid * 2 + nt) * 32 + lane];
                    uint32_t bh[2] = {v.x, v.z}, bl[2] = {v.y, v.w};
                    mmabf(acc[nt], Ah, bh);
                    mmabf(acc[nt], Ah, bl);
                    mmabf(acc[nt], Al, bh);
                }
            }
            #pragma unroll
            for (int nt = 0; nt < 2; nt++) {
                uint2 pr = bsplit2(acc[nt][0], acc[nt][1]);
                uint2* dst = (uint2*)&cB[(lg * 16 + wid) * 32 + h * 4 + lc];
                dst[nt] = pr;
            }
        }
    }
    __syncthreads();

    // ---- scores via bf16 mma: warp = (anchor a = wid>>1, M-tile mt = wid&1) ----
    {
        const int a = wid >> 1, mt = wid & 1;
        const float* xb = x_nei + (size_t)(b0 + a) * (KN * Dn);
        const int r0 = mt * 16 + lg, r1 = r0 + 8;
        float acc[4] = {0.f, 0.f, 0.f, 0.f};
        #pragma unroll 4
        for (int ks = 0; ks < 16; ks++) {
            const int kb = ks * 16 + 2 * lc;
            float2 x0 = *(const float2*)&xb[r0 * Dn + kb];
            float2 x1 = *(const float2*)&xb[r1 * Dn + kb];
            float2 x2 = *(const float2*)&xb[r0 * Dn + kb + 8];
            float2 x3 = *(const float2*)&xb[r1 * Dn + kb + 8];
            uint32_t Ah[4], Al[4];
            asplit(x0.x, x0.y, Ah[0], Al[0]);
            asplit(x1.x, x1.y, Ah[1], Al[1]);
            asplit(x2.x, x2.y, Ah[2], Al[2]);
            asplit(x3.x, x3.y, Ah[3], Al[3]);
            uint4 v = cB[(a * 16 + ks) * 32 + lane];
            uint32_t bh[2] = {v.x, v.z}, bl[2] = {v.y, v.w};
            mmabf(acc, Ah, bh);
            mmabf(acc, Ah, bl);
            mmabf(acc, Al, bh);
        }
        sS[(a * 8 + 2 * lc)     * 33 + r0] = acc[0];
        sS[(a * 8 + 2 * lc + 1) * 33 + r0] = acc[1];
        sS[(a * 8 + 2 * lc)     * 33 + r1] = acc[2];
        sS[(a * 8 + 2 * lc + 1) * 33 + r1] = acc[3];
    }
    __syncthreads();

    // ---- softmax -> split attn pairs aB[a*8+h][pair] ----
    {
        #pragma unroll
        for (int rr = 0; rr < 4; rr++) {
            const int r = wid * 4 + rr;
            float sc = sS[r * 33 + lane] * 0.17677669529663687f;
            float m = sc;
            #pragma unroll
            for (int o = 16; o; o >>= 1)
                m = fmaxf(m, __shfl_xor_sync(0xffffffffu, m, o));
            float e = expf(sc - m), es = e;
            #pragma unroll
            for (int o = 16; o; o >>= 1)
                es += __shfl_xor_sync(0xffffffffu, es, o);
            float at = e / es;
            float a0v = __shfl_sync(0xffffffffu, at, 2 * (lane & 15));
            float a1v = __shfl_sync(0xffffffffu, at, 2 * (lane & 15) + 1);
            if (lane < 16)
                aB[r * 16 + lane] = bsplit2(a0v, a1v);
        }
    }
    __syncthreads();

    // ---- u via bf16 mma: warp = (anchor a = wid>>1, col-half ch = wid&1) ----
    // u[h][col] = sum_k attn[h][k] * x[k][col]; M=8 heads, K=32 nei, N=128 cols.
    {
        const int a = wid >> 1, ch = wid & 1;
        const float* xb = x_nei + (size_t)(b0 + a) * (KN * Dn);
        // hoist A-frags (shared across all 16 ntiles)
        uint32_t Ah[2][4], Al[2][4];
        #pragma unroll
        for (int s = 0; s < 2; s++) {
            uint2 q0 = aB[(a * 8 + lg) * 16 + s * 8 + lc];
            uint2 q1 = aB[(a * 8 + lg) * 16 + s * 8 + 4 + lc];
            Ah[s][0] = q0.x; Al[s][0] = q0.y;
            Ah[s][2] = q1.x; Al[s][2] = q1.y;
            Ah[s][1] = Al[s][1] = Ah[s][3] = Al[s][3] = 0u;
        }
        __syncthreads();            // cB reads done before uB overwrite below
        #pragma unroll 4
        for (int nt = 0; nt < 16; nt++) {
            const int cb = ch * 128 + nt * 8 + lg;
            float acc[4] = {0.f, 0.f, 0.f, 0.f};
            #pragma unroll
            for (int s = 0; s < 2; s++) {
                const int kb = s * 16 + 2 * lc;
                float xv0 = xb[kb * Dn + cb];
                float xv1 = xb[(kb + 1) * Dn + cb];
                float xv2 = xb[(kb + 8) * Dn + cb];
                float xv3 = xb[(kb + 9) * Dn + cb];
                uint2 bp0 = bsplit2(xv0, xv1);
                uint2 bp1 = bsplit2(xv2, xv3);
                uint32_t bh[2] = {bp0.x, bp1.x}, bl[2] = {bp0.y, bp1.y};
                mmabf(acc, Ah[s], bh);
                mmabf(acc, Ah[s], bl);
                mmabf(acc, Al[s], bh);
            }
            // row lg = head, cols ch*128 + nt*8 + 2lc (+1)
            uB[(lg * 8 + a) * 130 + ch * 64 + nt * 4 + lc] = bsplit2(acc[0], acc[1]);
        }
    }
    __syncthreads();

    // ---- Wv (bf16 mma per head; warp-pair shares head; A pre-split in uB) ----
    {
        const int hd = wid >> 1;
        const int ntb = (wid & 1) * 2;
        float acc[2][4] = {{0.f,0.f,0.f,0.f},{0.f,0.f,0.f,0.f}};
        #pragma unroll
        for (int ks = 0; ks < 16; ks++) {
            uint2 q0 = uB[(hd * 8 + lg) * 130 + ks * 8 + lc];
            uint2 q1 = uB[(hd * 8 + lg) * 130 + ks * 8 + 4 + lc];
            uint32_t Ah[4], Al[4];
            Ah[0] = q0.x; Al[0] = q0.y;
            Ah[2] = q1.x; Al[2] = q1.y;
            Ah[1] = Al[1] = Ah[3] = Al[3] = 0u;
            #pragma unroll
            for (int uu = 0; uu < 2; uu++) {
                const int nt = ntb + uu;
                uint4 v = g_wvf[((hd * 16 + ks) * 4 + nt) * 32 + lane];
                uint32_t bh[2] = {v.x, v.z}, bl[2] = {v.y, v.w};
                mmabf(acc[uu], Ah, bh);
                mmabf(acc[uu], Ah, bl);
                mmabf(acc[uu], Al, bh);
            }
        }
        __syncthreads();
        #pragma unroll
        for (int uu = 0; uu < 2; uu++) {
            const int col = hd * 32 + (ntb + uu) * 8 + lc * 2;
            oS[lg * 268 + col]     = acc[uu][0];
            oS[lg * 268 + col + 1] = acc[uu][1];
        }
    }
    __syncthreads();

    // ---- x = x_anc + oS @ Wo (bf16 mma) ----
    {
        float acc[2][4] = {{0.f,0.f,0.f,0.f},{0.f,0.f,0.f,0.f}};
        #pragma unroll
        for (int ks = 0; ks < 16; ks++) {
            const int kb = ks * 16;
            float2 p0 = *(const float2*)&oS[lg * 268 + kb + 2 * lc];
            float2 p1 = *(const float2*)&oS[lg * 268 + kb + 8 + 2 * lc];
            uint32_t Ah[4], Al[4];
            asplit(p0.x, p0.y, Ah[0], Al[0]);
            asplit(p1.x, p1.y, Ah[2], Al[2]);
            Ah[1] = Al[1] = Ah[3] = Al[3] = 0u;
            #pragma unroll
            for (int nt = 0; nt < 2; nt++) {
                uint4 v = g_wof[(ks * 32 + wid * 2 + nt) * 32 + lane];
                uint32_t bh[2] = {v.x, v.z}, bl[2] = {v.y, v.w};
                mmabf(acc[nt], Ah, bh);
                mmabf(acc[nt], Ah, bl);
                mmabf(acc[nt], Al, bh);
            }
        }
        #pragma unroll
        for (int nt = 0; nt < 2; nt++) {
            const int col = wid * 16 + nt * 8 + lc * 2;
            const size_t idx = (size_t)(b0 + lg) * Dn + col;
            g_x[idx]     = x_anc[idx]     + acc[nt][0];
            g_x[idx + 1] = x_anc[idx + 1] + acc[nt][1];
        }
    }
}

// ---------------------------------------------------------------------------
// FFN (bf16 mma, 4 chunks of 256 FF-cols, 2 CTAs/SM): 32 rows / CTA.
// ---------------------------------------------------------------------------
__global__ __launch_bounds__(512, 2) void ffn_bf2(
    const float* __restrict__ ln2g, const float* __restrict__ ln2b,
    const float* __restrict__ ff1b, const float* __restrict__ ff2b,
    float* __restrict__ out)
{
    extern __shared__ uint2 su[];
    uint2* hHL = su;                      // [32][134]
    uint2* act = su + 32 * FH2;           // [32][131]

    const int tid = threadIdx.x, wid = tid >> 5, lane = tid & 31;
    const int lg = lane >> 2, lc = lane & 3;
    const int row0 = blockIdx.x * 32;

    #pragma unroll
    for (int rr = 0; rr < 2; rr++) {
        const int row = wid * 2 + rr;
        const float* xr = g_x + (size_t)(row0 + row) * Dn;
        float4 v0 = *(const float4*)&xr[lane * 8];
        float4 v1 = *(const float4*)&xr[lane * 8 + 4];
        float v[8] = {v0.x, v0.y, v0.z, v0.w, v1.x, v1.y, v1.z, v1.w};
        float s = 0.f, s2 = 0.f;
        #pragma unroll
        for (int t = 0; t < 8; t++) { s += v[t]; s2 += v[t] * v[t]; }
        #pragma unroll
        for (int o = 16; o; o >>= 1) {
            s  += __shfl_xor_sync(0xffffffffu, s,  o);
            s2 += __shfl_xor_sync(0xffffffffu, s2, o);
        }
        const float mu   = s * (1.0f / Dn);
        const float var  = s2 * (1.0f / Dn) - mu * mu;
        const float rstd = rsqrtf(var + 1e-5f);
        float hv[8];
        #pragma unroll
        for (int t = 0; t < 8; t++) {
            const int c = lane * 8 + t;
            hv[t] = (v[t] - mu) * rstd * ln2g[c] + ln2b[c];
        }
        #pragma unroll
        for (int t = 0; t < 4; t++)
            hHL[row * FH2 + lane * 4 + t] = bsplit2(hv[2 * t], hv[2 * t + 1]);
    }
    __syncthreads();

    float acc2[2][2][4];
    #pragma unroll
    for (int mt = 0; mt < 2; mt++)
        #pragma unroll
        for (int nt = 0; nt < 2; nt++)
            #pragma unroll
            for (int e = 0; e < 4; e++) acc2[mt][nt][e] = 0.f;

    for (int cc = 0; cc < 4; cc++) {
        float acc[2][2][4];
        #pragma unroll
        for (int mt = 0; mt < 2; mt++)
            #pragma unroll
            for (int nt = 0; nt < 2; nt++)
                #pragma unroll
                for (int e = 0; e < 4; e++) acc[mt][nt][e] = 0.f;

        // ---- ff1 chunk: 256 cols, warp covers 2 ntiles ----
        #pragma unroll 4
        for (int ks = 0; ks < 16; ks++) {
            const int kb2 = ks * 8;
            uint32_t Ah[2][4], Al[2][4];
            #pragma unroll
            for (int mt = 0; mt < 2; mt++) {
                const int r0 = mt * 16 + lg;
                uint2 q0 = hHL[r0 * FH2 + kb2 + lc];
                uint2 q1 = hHL[(r0 + 8) * FH2 + kb2 + lc];
                uint2 q2 = hHL[r0 * FH2 + kb2 + 4 + lc];
                uint2 q3 = hHL[(r0 + 8) * FH2 + kb2 + 4 + lc];
                Ah[mt][0] = q0.x; Al[mt][0] = q0.y;
                Ah[mt][1] = q1.x; Al[mt][1] = q1.y;
                Ah[mt][2] = q2.x; Al[mt][2] = q2.y;
                Ah[mt][3] = q3.x; Al[mt][3] = q3.y;
            }
            #pragma unroll
            for (int nt = 0; nt < 2; nt++) {
                const int ntile = cc * 32 + wid * 2 + nt;
                uint4 v = g_w1f[(ks * 128 + ntile) * 32 + lane];
                uint32_t bh[2] = {v.x, v.z}, bl[2] = {v.y, v.w};
                #pragma unroll
                for (int mt = 0; mt < 2; mt++) {
                    mmabf(acc[mt][nt], Ah[mt], bh);
                    mmabf(acc[mt][nt], Ah[mt], bl);
                    mmabf(acc[mt][nt], Al[mt], bh);
                }
            }
        }

        // ---- bias + gelu -> packed split act ----
        #pragma unroll
        for (int mt = 0; mt < 2; mt++) {
            const int r0 = mt * 16 + lg;
            #pragma unroll
            for (int nt = 0; nt < 2; nt++) {
                const int lcol = wid * 16 + nt * 8 + lc * 2;
                const int gcol = cc * 256 + lcol;
                const float b0 = ff1b[gcol], b1 = ff1b[gcol + 1];
                float u0 = acc[mt][nt][0] + b0;
                float u1 = acc[mt][nt][1] + b1;
                float u2 = acc[mt][nt][2] + b0;
                float u3 = acc[mt][nt][3] + b1;
                float g0 = 0.5f * u0 * (1.0f + erff(u0 * 0.70710678118654752f));
                float g1v = 0.5f * u1 * (1.0f + erff(u1 * 0.70710678118654752f));
                float g2 = 0.5f * u2 * (1.0f + erff(u2 * 0.70710678118654752f));
                float g3 = 0.5f * u3 * (1.0f + erff(u3 * 0.70710678118654752f));
                const int pidx = lcol >> 1;   // [0,128)
                act[r0 * FA2 + pidx]       = bsplit2(g0, g1v);
                act[(r0 + 8) * FA2 + pidx] = bsplit2(g2, g3);
            }
        }
        __syncthreads();

        // ---- ff2 partial over this chunk's 256 K-values ----
        #pragma unroll 4
        for (int ks = 0; ks < 16; ks++) {
            const int kb2 = ks * 8;
            uint32_t Ah[2][4], Al[2][4];
            #pragma unroll
            for (int mt = 0; mt < 2; mt++) {
                const int r0 = mt * 16 + lg;
                uint2 q0 = act[r0 * FA2 + kb2 + lc];
                uint2 q1 = act[(r0 + 8) * FA2 + kb2 + lc];
                uint2 q2 = act[r0 * FA2 + kb2 + 4 + lc];
                uint2 q3 = act[(r0 + 8) * FA2 + kb2 + 4 + lc];
                Ah[mt][0] = q0.x; Al[mt][0] = q0.y;
                Ah[mt][1] = q1.x; Al[mt][1] = q1.y;
                Ah[mt][2] = q2.x; Al[mt][2] = q2.y;
                Ah[mt][3] = q3.x; Al[mt][3] = q3.y;
            }
            const int ksg = cc * 16 + ks;
            #pragma unroll
            for (int nt = 0; nt < 2; nt++) {
                const int ntile = wid * 2 + nt;
                uint4 v = g_w2f[(ksg * 32 + ntile) * 32 + lane];
                uint32_t bh[2] = {v.x, v.z}, bl[2] = {v.y, v.w};
                #pragma unroll
                for (int mt = 0; mt < 2; mt++) {
                    mmabf(acc2[mt][nt], Ah[mt], bh);
                    mmabf(acc2[mt][nt], Ah[mt], bl);
                    mmabf(acc2[mt][nt], Al[mt], bh);
                }
            }
        }
        __syncthreads();
    }

    #pragma unroll
    for (int mt = 0; mt < 2; mt++) {
        const int r0 = mt * 16 + lg;
        #pragma unroll
        for (int nt = 0; nt < 2; nt++) {
            const int col = wid * 16 + nt * 8 + lc * 2;
            const float b0 = ff2b[col], b1 = ff2b[col + 1];
            const size_t i0 = (size_t)(row0 + r0) * Dn + col;
            const size_t i1 = (size_t)(row0 + r0 + 8) * Dn + col;
            out[i0]     = g_x[i0]     + acc2[mt][nt][0] + b0;
            out[i0 + 1] = g_x[i0 + 1] + acc2[mt][nt][1] + b1;
            out[i1]     = g_x[i1]     + acc2[mt][nt][2] + b0;
            out[i1 + 1] = g_x[i1 + 1] + acc2[mt][nt][3] + b1;
        }
    }
}

extern "C" void kernel_launch(void* const* d_in, const int* in_sizes, int n_in,
                              void* d_out, int out_size)
{
    const float* x_anc = (const float*)d_in[0];
    const float* x_nei = (const float*)d_in[1];
    const float* Wq    = (const float*)d_in[2];
    const float* Wk    = (const float*)d_in[3];
    const float* Wv    = (const float*)d_in[4];
    const float* Wo    = (const float*)d_in[5];
    const float* ln1g  = (const float*)d_in[6];
    const float* ln1b  = (const float*)d_in[7];
    const float* ln2g  = (const float*)d_in[8];
    const float* ln2b  = (const float*)d_in[9];
    const float* ff1w  = (const float*)d_in[10];
    const float* ff1b  = (const float*)d_in[11];
    const float* ff2w  = (const float*)d_in[12];
    const float* ff2b  = (const float*)d_in[13];
    float* out = (float*)d_out;

    static bool attr_set = false;
    if (!attr_set) {
        cudaFuncSetAttribute(attn12,  cudaFuncAttributeMaxDynamicSharedMemorySize, ATTN_SMEM);
        cudaFuncSetAttribute(ffn_bf2, cudaFuncAttributeMaxDynamicSharedMemorySize, FFN_SMEM);
        attr_set = true;
    }

    split_all<<<768, 256>>>(Wq, Wk, Wv, Wo, ff1w, ff2w);
    attn12<<<Bn / 8, 512, ATTN_SMEM>>>(x_anc, x_nei, ln1g, ln1b);
    ffn_bf2<<<Bn / 32, 512, FFN_SMEM>>>(ln2g, ln2b, ff1b, ff2b, out);
}